// round 2
// baseline (speedup 1.0000x reference)
#include <cuda_runtime.h>
#include <math.h>

#define B_ 4
#define N_ 65536
#define K_ 16
#define D_ 8
#define OUT_ 8
#define EPS_ 1e-6f
#define SLOPE_ 0.2f

// 16 floats per point: [x,y,z,pad, f0..f7, pad x4] -> 64B record, sector aligned
__device__ float4 g_rec[(size_t)B_ * N_ * 4];
__device__ double g_sums[16];          // sum_y[0..7], sum_y2[8..15]
__device__ float  g_wp[64];            // [0..7]=W0, [8+o*3+i]=A, [32+o*3+i]=C, [56..63]=bias
__device__ float  g_scale[8];
__device__ float  g_shift[8];

// ---------------- Pass 0: pack records, zero stats, prep weights ----------------
__global__ void __launch_bounds__(256) k0_pack(const float* __restrict__ coords,
                                               const float* __restrict__ feats,
                                               const float* __restrict__ conv_w,
                                               const float* __restrict__ conv_b) {
    int t = blockIdx.x * blockDim.x + threadIdx.x;
    if (blockIdx.x == 0) {
        if (threadIdx.x < 16) g_sums[threadIdx.x] = 0.0;
        if (threadIdx.x < 8) {
            int o = threadIdx.x;
            const float* w = conv_w + o * 10;
            g_wp[o] = w[0];
            #pragma unroll
            for (int i = 0; i < 3; i++) {
                g_wp[8  + o * 3 + i] = w[1 + i] + w[4 + i];   // A: ext coeff
                g_wp[32 + o * 3 + i] = w[7 + i] - w[1 + i];   // C: nb coeff
            }
            g_wp[56 + o] = conv_b[o];
        }
    }
    if (t >= B_ * N_) return;
    int b = t >> 16;
    int n = t & (N_ - 1);
    float4 c4;
    c4.x = coords[(size_t)t * 3 + 0];
    c4.y = coords[(size_t)t * 3 + 1];
    c4.z = coords[(size_t)t * 3 + 2];
    c4.w = 0.f;
    const float* fb = feats + (size_t)b * D_ * N_ + n;
    float4 f0, f1;
    f0.x = fb[0 * N_]; f0.y = fb[1 * N_]; f0.z = fb[2 * N_]; f0.w = fb[3 * N_];
    f1.x = fb[4 * N_]; f1.y = fb[5 * N_]; f1.z = fb[6 * N_]; f1.w = fb[7 * N_];
    float4* r = &g_rec[(size_t)t * 4];
    r[0] = c4; r[1] = f0; r[2] = f1;
}

// ---------------- Pass 1: BN statistics (sum, sumsq per channel) ----------------
__global__ void __launch_bounds__(256) k1_stats(const int* __restrict__ idx) {
    int t = blockIdx.x * blockDim.x + threadIdx.x;   // one (b,n) per thread
    int b = t >> 16;
    int base = b << 16;
    const float4* rec = g_rec;
    float4 ext = rec[(size_t)t * 4];

    float e[8], W0[8], C[24];
    #pragma unroll
    for (int o = 0; o < 8; o++) {
        W0[o] = g_wp[o];
        e[o]  = g_wp[56 + o] + g_wp[8 + o * 3] * ext.x + g_wp[9 + o * 3] * ext.y
                             + g_wp[10 + o * 3] * ext.z;
        C[o * 3 + 0] = g_wp[32 + o * 3];
        C[o * 3 + 1] = g_wp[33 + o * 3];
        C[o * 3 + 2] = g_wp[34 + o * 3];
    }

    float sy[8], sy2[8];
    #pragma unroll
    for (int o = 0; o < 8; o++) { sy[o] = 0.f; sy2[o] = 0.f; }

    const int4* ip = (const int4*)idx + (size_t)t * 4;
    #pragma unroll
    for (int kk = 0; kk < 4; kk++) {
        int4 j4 = ip[kk];
        int js[4] = {j4.x, j4.y, j4.z, j4.w};
        #pragma unroll
        for (int u = 0; u < 4; u++) {
            float4 nb = rec[(size_t)(base + js[u]) * 4];
            float rx = ext.x - nb.x, ry = ext.y - nb.y, rz = ext.z - nb.z;
            float d = sqrtf(rx * rx + ry * ry + rz * rz);
            #pragma unroll
            for (int o = 0; o < 8; o++) {
                float y = e[o] + W0[o] * d + C[o*3] * nb.x + C[o*3+1] * nb.y + C[o*3+2] * nb.z;
                sy[o]  += y;
                sy2[o] += y * y;
            }
        }
    }

    // warp reduce
    #pragma unroll
    for (int o = 0; o < 8; o++) {
        #pragma unroll
        for (int off = 16; off > 0; off >>= 1) {
            sy[o]  += __shfl_down_sync(0xffffffffu, sy[o],  off);
            sy2[o] += __shfl_down_sync(0xffffffffu, sy2[o], off);
        }
    }
    __shared__ float ps[16];
    if (threadIdx.x < 16) ps[threadIdx.x] = 0.f;
    __syncthreads();
    if ((threadIdx.x & 31) == 0) {
        #pragma unroll
        for (int o = 0; o < 8; o++) {
            atomicAdd(&ps[o],     sy[o]);
            atomicAdd(&ps[8 + o], sy2[o]);
        }
    }
    __syncthreads();
    if (threadIdx.x < 16) atomicAdd(&g_sums[threadIdx.x], (double)ps[threadIdx.x]);
}

// ---------------- Pass 1.5: finalize BN scale/shift ----------------
__global__ void k2_final(const float* __restrict__ gamma, const float* __restrict__ beta) {
    int o = threadIdx.x;
    if (o < 8) {
        double M    = (double)B_ * N_ * K_;
        double mean = g_sums[o] / M;
        double var  = g_sums[8 + o] / M - mean * mean;
        float  sc   = (float)((double)gamma[o] / sqrt(var + (double)EPS_));
        g_scale[o]  = sc;
        g_shift[o]  = beta[o] - (float)mean * sc;
    }
}

// ---------------- Pass 2: recompute y, apply BN+LeakyReLU, write both outputs ----------------
__global__ void __launch_bounds__(256) k3_out(const int* __restrict__ idx,
                                              float* __restrict__ out) {
    int t  = blockIdx.x * blockDim.x + threadIdx.x;  // [0, B*N*4)
    int kg = t & 3;
    int pn = t >> 2;               // b*N + n
    int b  = pn >> 16;
    int n  = pn & (N_ - 1);
    int base = b << 16;

    const float4* rec = g_rec;
    float4 ext = rec[(size_t)pn * 4];

    float e[8], W0[8], C[24];
    #pragma unroll
    for (int o = 0; o < 8; o++) {
        W0[o] = g_wp[o];
        e[o]  = g_wp[56 + o] + g_wp[8 + o * 3] * ext.x + g_wp[9 + o * 3] * ext.y
                             + g_wp[10 + o * 3] * ext.z;
        C[o * 3 + 0] = g_wp[32 + o * 3];
        C[o * 3 + 1] = g_wp[33 + o * 3];
        C[o * 3 + 2] = g_wp[34 + o * 3];
    }

    int4 j4 = ((const int4*)idx)[(size_t)pn * 4 + kg];
    int js[4] = {j4.x, j4.y, j4.z, j4.w};

    float ybuf[4][8];
    float fbuf[4][8];
    #pragma unroll
    for (int u = 0; u < 4; u++) {
        size_t ro = (size_t)(base + js[u]) * 4;
        float4 nb = rec[ro];
        float4 f0 = rec[ro + 1];
        float4 f1 = rec[ro + 2];
        fbuf[u][0] = f0.x; fbuf[u][1] = f0.y; fbuf[u][2] = f0.z; fbuf[u][3] = f0.w;
        fbuf[u][4] = f1.x; fbuf[u][5] = f1.y; fbuf[u][6] = f1.z; fbuf[u][7] = f1.w;
        float rx = ext.x - nb.x, ry = ext.y - nb.y, rz = ext.z - nb.z;
        float d = sqrtf(rx * rx + ry * ry + rz * rz);
        #pragma unroll
        for (int o = 0; o < 8; o++) {
            ybuf[u][o] = e[o] + W0[o] * d + C[o*3] * nb.x + C[o*3+1] * nb.y + C[o*3+2] * nb.z;
        }
    }

    const size_t plane = (size_t)N_ * K_;                 // 1M elems per (b,c) plane
    const size_t pos   = (size_t)n * K_ + (size_t)kg * 4;
    float* o1 = out + (size_t)b * 16 * plane + pos;                       // (B,16,N,K)
    float* o2 = out + (size_t)B_ * 16 * plane + (size_t)b * 8 * plane + pos; // (B,8,N,K)

    // neighbour-feature channels 0..7
    #pragma unroll
    for (int d = 0; d < 8; d++) {
        float4 v = make_float4(fbuf[0][d], fbuf[1][d], fbuf[2][d], fbuf[3][d]);
        *(float4*)(o1 + (size_t)d * plane) = v;
    }
    // BN + LeakyReLU channels 8..15 (and second output)
    #pragma unroll
    for (int o = 0; o < 8; o++) {
        float sc = g_scale[o], sh = g_shift[o];
        float4 v;
        v.x = fmaf(ybuf[0][o], sc, sh);
        v.y = fmaf(ybuf[1][o], sc, sh);
        v.z = fmaf(ybuf[2][o], sc, sh);
        v.w = fmaf(ybuf[3][o], sc, sh);
        v.x = fmaxf(v.x, SLOPE_ * v.x);
        v.y = fmaxf(v.y, SLOPE_ * v.y);
        v.z = fmaxf(v.z, SLOPE_ * v.z);
        v.w = fmaxf(v.w, SLOPE_ * v.w);
        *(float4*)(o1 + (size_t)(8 + o) * plane) = v;
        *(float4*)(o2 + (size_t)o * plane)       = v;
    }
}

extern "C" void kernel_launch(void* const* d_in, const int* in_sizes, int n_in,
                              void* d_out, int out_size) {
    const float* coords = (const float*)d_in[0];
    const float* feats  = (const float*)d_in[1];
    const int*   idx    = (const int*)d_in[2];
    const float* conv_w = (const float*)d_in[3];
    const float* conv_b = (const float*)d_in[4];
    const float* gamma  = (const float*)d_in[5];
    const float* beta   = (const float*)d_in[6];
    float* out = (float*)d_out;

    k0_pack<<<(B_ * N_ + 255) / 256, 256>>>(coords, feats, conv_w, conv_b);
    k1_stats<<<(B_ * N_) / 256, 256>>>(idx);
    k2_final<<<1, 32>>>(gamma, beta);
    k3_out<<<(B_ * N_ * 4) / 256, 256>>>(idx, out);
}

// round 3
// speedup vs baseline: 1.0210x; 1.0210x over previous
#include <cuda_runtime.h>
#include <math.h>

#define B_ 4
#define N_ 65536
#define K_ 16
#define D_ 8
#define OUT_ 8
#define EPS_ 1e-6f
#define SLOPE_ 0.2f

// 64B record per point: [x,y,z,pad | f0..f3 | f4..f7 | pad]
__device__ float4 g_rec[(size_t)B_ * N_ * 4];
__device__ float4 g_e[(size_t)B_ * N_ * 2];   // per-point e[8] = bias + A·ext
__device__ double g_sums[16];                 // sum_y[0..7], sum_y2[8..15]
__device__ float  g_wp[64];                   // [0..7]=W0, [8..31]=A, [32..55]=C, [56..63]=bias
__device__ float  g_bn[16];                   // scale[0..7], shift[8..15]

__constant__ float c_wp[64];
__constant__ float c_bn[16];

// ---------------- prep: weight transforms + zero stats ----------------
__global__ void k_prep(const float* __restrict__ conv_w, const float* __restrict__ conv_b) {
    int o = threadIdx.x;
    if (o < 16) g_sums[o] = 0.0;
    if (o < 8) {
        const float* w = conv_w + o * 10;
        g_wp[o] = w[0];                                   // W0 (dist coeff)
        #pragma unroll
        for (int i = 0; i < 3; i++) {
            g_wp[8  + o * 3 + i] = w[1 + i] + w[4 + i];   // A: ext coeff
            g_wp[32 + o * 3 + i] = w[7 + i] - w[1 + i];   // C: nb coeff
        }
        g_wp[56 + o] = conv_b[o];
    }
}

// ---------------- Pass 0: pack records + per-point e[8] ----------------
__global__ void __launch_bounds__(256) k0_pack(const float* __restrict__ coords,
                                               const float* __restrict__ feats) {
    int t = blockIdx.x * blockDim.x + threadIdx.x;
    if (t >= B_ * N_) return;
    int b = t >> 16;
    int n = t & (N_ - 1);
    float cx = coords[(size_t)t * 3 + 0];
    float cy = coords[(size_t)t * 3 + 1];
    float cz = coords[(size_t)t * 3 + 2];
    const float* fb = feats + (size_t)b * D_ * N_ + n;
    float4 f0, f1;
    f0.x = fb[0 * N_]; f0.y = fb[1 * N_]; f0.z = fb[2 * N_]; f0.w = fb[3 * N_];
    f1.x = fb[4 * N_]; f1.y = fb[5 * N_]; f1.z = fb[6 * N_]; f1.w = fb[7 * N_];
    float4* r = &g_rec[(size_t)t * 4];
    r[0] = make_float4(cx, cy, cz, 0.f);
    r[1] = f0;
    r[2] = f1;

    float e[8];
    #pragma unroll
    for (int o = 0; o < 8; o++) {
        e[o] = c_wp[56 + o] + c_wp[8 + o*3] * cx + c_wp[9 + o*3] * cy + c_wp[10 + o*3] * cz;
    }
    g_e[(size_t)t * 2 + 0] = make_float4(e[0], e[1], e[2], e[3]);
    g_e[(size_t)t * 2 + 1] = make_float4(e[4], e[5], e[6], e[7]);
}

// ---------------- Pass 1: BN statistics ----------------
__global__ void __launch_bounds__(256, 3) k1_stats(const int* __restrict__ idx) {
    int t = blockIdx.x * blockDim.x + threadIdx.x;   // one (b,n) per thread
    int b = t >> 16;
    int base = b << 16;
    const float4* rec = g_rec;
    float4 ext = rec[(size_t)t * 4];

    float4 e01 = g_e[(size_t)t * 2 + 0];
    float4 e23 = g_e[(size_t)t * 2 + 1];
    float e[8] = {e01.x, e01.y, e01.z, e01.w, e23.x, e23.y, e23.z, e23.w};

    float sy[8], sy2[8];
    #pragma unroll
    for (int o = 0; o < 8; o++) { sy[o] = 0.f; sy2[o] = 0.f; }

    const int4* ip = (const int4*)idx + (size_t)t * 4;
    #pragma unroll
    for (int kk = 0; kk < 4; kk++) {
        int4 j4 = ip[kk];
        int js[4] = {j4.x, j4.y, j4.z, j4.w};
        #pragma unroll
        for (int u = 0; u < 4; u++) {
            float4 nb = rec[(size_t)(base + js[u]) * 4];
            float rx = ext.x - nb.x, ry = ext.y - nb.y, rz = ext.z - nb.z;
            float d = sqrtf(rx * rx + ry * ry + rz * rz);
            #pragma unroll
            for (int o = 0; o < 8; o++) {
                float y = e[o] + c_wp[o] * d + c_wp[32 + o*3] * nb.x
                        + c_wp[33 + o*3] * nb.y + c_wp[34 + o*3] * nb.z;
                sy[o]  += y;
                sy2[o] += y * y;
            }
        }
    }

    #pragma unroll
    for (int o = 0; o < 8; o++) {
        #pragma unroll
        for (int off = 16; off > 0; off >>= 1) {
            sy[o]  += __shfl_down_sync(0xffffffffu, sy[o],  off);
            sy2[o] += __shfl_down_sync(0xffffffffu, sy2[o], off);
        }
    }
    __shared__ float ps[16];
    if (threadIdx.x < 16) ps[threadIdx.x] = 0.f;
    __syncthreads();
    if ((threadIdx.x & 31) == 0) {
        #pragma unroll
        for (int o = 0; o < 8; o++) {
            atomicAdd(&ps[o],     sy[o]);
            atomicAdd(&ps[8 + o], sy2[o]);
        }
    }
    __syncthreads();
    if (threadIdx.x < 16) atomicAdd(&g_sums[threadIdx.x], (double)ps[threadIdx.x]);
}

// ---------------- Pass 1.5: finalize BN scale/shift ----------------
__global__ void k2_final(const float* __restrict__ gamma, const float* __restrict__ beta) {
    int o = threadIdx.x;
    if (o < 8) {
        double M    = (double)B_ * N_ * K_;
        double mean = g_sums[o] / M;
        double var  = g_sums[8 + o] / M - mean * mean;
        float  sc   = (float)((double)gamma[o] / sqrt(var + (double)EPS_));
        g_bn[o]     = sc;
        g_bn[8 + o] = beta[o] - (float)mean * sc;
    }
}

// ---------------- Pass 2: one thread per neighbour ----------------
__global__ void __launch_bounds__(256, 4) k3_out(const int* __restrict__ idx,
                                                 float* __restrict__ out) {
    int t  = blockIdx.x * blockDim.x + threadIdx.x;  // [0, B*N*K)
    int pn = t >> 4;               // b*N + n
    int b  = pn >> 16;

    int j = __ldg(idx + t);
    const float4* rp = g_rec + ((size_t)((b << 16) | j) << 2);
    float4 nb = rp[0];
    float4 f0 = rp[1];
    float4 f1 = rp[2];

    float4 ext = g_rec[(size_t)pn << 2];            // broadcast within warp
    float rx = ext.x - nb.x, ry = ext.y - nb.y, rz = ext.z - nb.z;
    float d = sqrtf(rx * rx + ry * ry + rz * rz);

    float4 e01 = g_e[(size_t)pn * 2 + 0];
    float4 e23 = g_e[(size_t)pn * 2 + 1];
    float e[8] = {e01.x, e01.y, e01.z, e01.w, e23.x, e23.y, e23.z, e23.w};

    const size_t plane = (size_t)N_ * K_;           // 1,048,576
    size_t inner = (size_t)(t & (int)(plane - 1));  // n*K + k
    float* o1 = out + (size_t)b * 16 * plane + inner;                          // (B,16,N,K)
    float* o2 = out + (size_t)B_ * 16 * plane + (size_t)b * 8 * plane + inner; // (B,8,N,K)

    // neighbour-feature channels 0..7 (coalesced STG.32 across warp)
    o1[0 * plane] = f0.x; o1[1 * plane] = f0.y; o1[2 * plane] = f0.z; o1[3 * plane] = f0.w;
    o1[4 * plane] = f1.x; o1[5 * plane] = f1.y; o1[6 * plane] = f1.z; o1[7 * plane] = f1.w;

    // BN + LeakyReLU channels
    #pragma unroll
    for (int o = 0; o < 8; o++) {
        float y = e[o] + c_wp[o] * d + c_wp[32 + o*3] * nb.x
                + c_wp[33 + o*3] * nb.y + c_wp[34 + o*3] * nb.z;
        float z = fmaf(y, c_bn[o], c_bn[8 + o]);
        z = fmaxf(z, SLOPE_ * z);
        o1[(size_t)(8 + o) * plane] = z;
        o2[(size_t)o * plane]       = z;
    }
}

extern "C" void kernel_launch(void* const* d_in, const int* in_sizes, int n_in,
                              void* d_out, int out_size) {
    const float* coords = (const float*)d_in[0];
    const float* feats  = (const float*)d_in[1];
    const int*   idx    = (const int*)d_in[2];
    const float* conv_w = (const float*)d_in[3];
    const float* conv_b = (const float*)d_in[4];
    const float* gamma  = (const float*)d_in[5];
    const float* beta   = (const float*)d_in[6];
    float* out = (float*)d_out;

    void *c_wp_p = nullptr, *c_bn_p = nullptr, *g_wp_p = nullptr, *g_bn_p = nullptr;
    cudaGetSymbolAddress(&c_wp_p, c_wp);
    cudaGetSymbolAddress(&c_bn_p, c_bn);
    cudaGetSymbolAddress(&g_wp_p, g_wp);
    cudaGetSymbolAddress(&g_bn_p, g_bn);

    k_prep<<<1, 32>>>(conv_w, conv_b);
    cudaMemcpyAsync(c_wp_p, g_wp_p, 64 * sizeof(float), cudaMemcpyDeviceToDevice, 0);
    k0_pack<<<(B_ * N_ + 255) / 256, 256>>>(coords, feats);
    k1_stats<<<(B_ * N_) / 256, 256>>>(idx);
    k2_final<<<1, 32>>>(gamma, beta);
    cudaMemcpyAsync(c_bn_p, g_bn_p, 16 * sizeof(float), cudaMemcpyDeviceToDevice, 0);
    k3_out<<<(B_ * N_ * K_) / 256, 256>>>(idx, out);
}

// round 4
// speedup vs baseline: 1.0953x; 1.0728x over previous
#include <cuda_runtime.h>
#include <cuda_fp16.h>
#include <math.h>

#define B_ 4
#define N_ 65536
#define K_ 16
#define D_ 8
#define EPS_ 1e-6f
#define SLOPE_ 0.2f

// 32B record per point: [x,y,z,pad (fp32) | f0..f7 (fp16)]
__device__ float4 g_rec[(size_t)B_ * N_ * 2];
__device__ float4 g_e[(size_t)B_ * N_ * 2];   // per-point e[8] = bias + A·ext
__device__ double g_sums[16];                 // sum_y[0..7], sum_y2[8..15]
__device__ float  g_wp[64];                   // [0..7]=W0, [8..31]=A, [32..55]=C, [56..63]=bias
__constant__ float c_wp[64];

// ---------------- Pass 0: pack records + per-point e[8]; block0 preps weights/stats ----------------
__global__ void __launch_bounds__(256) k0_pack(const float* __restrict__ coords,
                                               const float* __restrict__ feats,
                                               const float* __restrict__ conv_w,
                                               const float* __restrict__ conv_b) {
    __shared__ float sA[24], sb[8];
    if (threadIdx.x < 8) {
        int o = threadIdx.x;
        const float* w = conv_w + o * 10;
        float a0 = w[1] + w[4], a1 = w[2] + w[5], a2 = w[3] + w[6];
        sA[o * 3 + 0] = a0; sA[o * 3 + 1] = a1; sA[o * 3 + 2] = a2;
        sb[o] = conv_b[o];
        if (blockIdx.x == 0) {
            g_wp[o]      = w[0];
            g_wp[8 + o*3 + 0] = a0; g_wp[8 + o*3 + 1] = a1; g_wp[8 + o*3 + 2] = a2;
            g_wp[32 + o*3 + 0] = w[7] - w[1];
            g_wp[32 + o*3 + 1] = w[8] - w[2];
            g_wp[32 + o*3 + 2] = w[9] - w[3];
            g_wp[56 + o] = conv_b[o];
            g_sums[o] = 0.0; g_sums[8 + o] = 0.0;
        }
    }
    __syncthreads();

    int t = blockIdx.x * blockDim.x + threadIdx.x;
    if (t >= B_ * N_) return;
    int b = t >> 16;
    int n = t & (N_ - 1);
    float cx = coords[(size_t)t * 3 + 0];
    float cy = coords[(size_t)t * 3 + 1];
    float cz = coords[(size_t)t * 3 + 2];

    const float* fb = feats + (size_t)b * D_ * N_ + n;
    __half2 h01 = __floats2half2_rn(fb[0 * N_], fb[1 * N_]);
    __half2 h23 = __floats2half2_rn(fb[2 * N_], fb[3 * N_]);
    __half2 h45 = __floats2half2_rn(fb[4 * N_], fb[5 * N_]);
    __half2 h67 = __floats2half2_rn(fb[6 * N_], fb[7 * N_]);
    float4 hv;
    hv.x = __uint_as_float(*(const unsigned*)&h01);
    hv.y = __uint_as_float(*(const unsigned*)&h23);
    hv.z = __uint_as_float(*(const unsigned*)&h45);
    hv.w = __uint_as_float(*(const unsigned*)&h67);

    float4* r = &g_rec[(size_t)t * 2];
    r[0] = make_float4(cx, cy, cz, 0.f);
    r[1] = hv;

    float e[8];
    #pragma unroll
    for (int o = 0; o < 8; o++)
        e[o] = sb[o] + sA[o*3] * cx + sA[o*3+1] * cy + sA[o*3+2] * cz;
    g_e[(size_t)t * 2 + 0] = make_float4(e[0], e[1], e[2], e[3]);
    g_e[(size_t)t * 2 + 1] = make_float4(e[4], e[5], e[6], e[7]);
}

// ---------------- Pass 1: BN statistics ----------------
__global__ void __launch_bounds__(256, 4) k1_stats(const int* __restrict__ idx) {
    int t = blockIdx.x * blockDim.x + threadIdx.x;   // one (b,n) per thread
    int base = (t >> 16) << 16;
    const float4* rec = g_rec;
    float4 ext = rec[(size_t)t * 2];

    float4 e01 = g_e[(size_t)t * 2 + 0];
    float4 e23 = g_e[(size_t)t * 2 + 1];
    float e[8] = {e01.x, e01.y, e01.z, e01.w, e23.x, e23.y, e23.z, e23.w};

    float sy[8], sy2[8];
    #pragma unroll
    for (int o = 0; o < 8; o++) { sy[o] = 0.f; sy2[o] = 0.f; }

    const int4* ip = (const int4*)idx + (size_t)t * 4;
    #pragma unroll
    for (int kk = 0; kk < 4; kk++) {
        int4 j4 = ip[kk];
        int js[4] = {j4.x, j4.y, j4.z, j4.w};
        #pragma unroll
        for (int u = 0; u < 4; u++) {
            float4 nb = rec[(size_t)(base + js[u]) * 2];
            float rx = ext.x - nb.x, ry = ext.y - nb.y, rz = ext.z - nb.z;
            float d = sqrtf(rx * rx + ry * ry + rz * rz);
            #pragma unroll
            for (int o = 0; o < 8; o++) {
                float y = e[o] + c_wp[o] * d + c_wp[32 + o*3] * nb.x
                        + c_wp[33 + o*3] * nb.y + c_wp[34 + o*3] * nb.z;
                sy[o]  += y;
                sy2[o] += y * y;
            }
        }
    }

    #pragma unroll
    for (int o = 0; o < 8; o++) {
        #pragma unroll
        for (int off = 16; off > 0; off >>= 1) {
            sy[o]  += __shfl_down_sync(0xffffffffu, sy[o],  off);
            sy2[o] += __shfl_down_sync(0xffffffffu, sy2[o], off);
        }
    }
    __shared__ float ps[16];
    if (threadIdx.x < 16) ps[threadIdx.x] = 0.f;
    __syncthreads();
    if ((threadIdx.x & 31) == 0) {
        #pragma unroll
        for (int o = 0; o < 8; o++) {
            atomicAdd(&ps[o],     sy[o]);
            atomicAdd(&ps[8 + o], sy2[o]);
        }
    }
    __syncthreads();
    if (threadIdx.x < 16) atomicAdd(&g_sums[threadIdx.x], (double)ps[threadIdx.x]);
}

// ---------------- Pass 2: one thread per neighbour; BN finalize per block ----------------
__global__ void __launch_bounds__(256, 5) k3_out(const int* __restrict__ idx,
                                                 const float* __restrict__ gamma,
                                                 const float* __restrict__ beta,
                                                 float* __restrict__ out) {
    __shared__ float s_bn[16];    // scale[0..7], shift[8..15]
    if (threadIdx.x < 8) {
        int o = threadIdx.x;
        double M    = (double)B_ * N_ * K_;
        double mean = g_sums[o] / M;
        double var  = g_sums[8 + o] / M - mean * mean;
        float  sc   = (float)((double)gamma[o] / sqrt(var + (double)EPS_));
        s_bn[o]     = sc;
        s_bn[8 + o] = beta[o] - (float)mean * sc;
    }
    __syncthreads();

    int t  = blockIdx.x * blockDim.x + threadIdx.x;  // [0, B*N*K)
    int pn = t >> 4;               // b*N + n
    int b  = pn >> 16;

    int j = __ldg(idx + t);
    const float4* rp = g_rec + ((size_t)((b << 16) | j) << 1);
    float4 nb = rp[0];
    float4 hf = rp[1];

    float4 ext = g_rec[(size_t)pn << 1];            // broadcast within warp
    float rx = ext.x - nb.x, ry = ext.y - nb.y, rz = ext.z - nb.z;
    float d = sqrtf(rx * rx + ry * ry + rz * rz);

    float4 e01 = g_e[(size_t)pn * 2 + 0];
    float4 e23 = g_e[(size_t)pn * 2 + 1];
    float e[8] = {e01.x, e01.y, e01.z, e01.w, e23.x, e23.y, e23.z, e23.w};

    // unpack fp16 features
    unsigned u0 = __float_as_uint(hf.x), u1 = __float_as_uint(hf.y);
    unsigned u2 = __float_as_uint(hf.z), u3 = __float_as_uint(hf.w);
    float2 f01 = __half22float2(*(__half2*)&u0);
    float2 f23 = __half22float2(*(__half2*)&u1);
    float2 f45 = __half22float2(*(__half2*)&u2);
    float2 f67 = __half22float2(*(__half2*)&u3);

    const size_t plane = (size_t)N_ * K_;           // 1,048,576
    size_t inner = (size_t)(t & (int)(plane - 1));  // n*K + k
    float* o1 = out + (size_t)b * 16 * plane + inner;                          // (B,16,N,K)
    float* o2 = out + (size_t)B_ * 16 * plane + (size_t)b * 8 * plane + inner; // (B,8,N,K)

    // neighbour-feature channels 0..7 (coalesced STG.32 across warp)
    o1[0 * plane] = f01.x; o1[1 * plane] = f01.y;
    o1[2 * plane] = f23.x; o1[3 * plane] = f23.y;
    o1[4 * plane] = f45.x; o1[5 * plane] = f45.y;
    o1[6 * plane] = f67.x; o1[7 * plane] = f67.y;

    // BN + LeakyReLU channels
    #pragma unroll
    for (int o = 0; o < 8; o++) {
        float y = e[o] + c_wp[o] * d + c_wp[32 + o*3] * nb.x
                + c_wp[33 + o*3] * nb.y + c_wp[34 + o*3] * nb.z;
        float z = fmaf(y, s_bn[o], s_bn[8 + o]);
        z = fmaxf(z, SLOPE_ * z);
        o1[(size_t)(8 + o) * plane] = z;
        o2[(size_t)o * plane]       = z;
    }
}

extern "C" void kernel_launch(void* const* d_in, const int* in_sizes, int n_in,
                              void* d_out, int out_size) {
    const float* coords = (const float*)d_in[0];
    const float* feats  = (const float*)d_in[1];
    const int*   idx    = (const int*)d_in[2];
    const float* conv_w = (const float*)d_in[3];
    const float* conv_b = (const float*)d_in[4];
    const float* gamma  = (const float*)d_in[5];
    const float* beta   = (const float*)d_in[6];
    float* out = (float*)d_out;

    void *c_wp_p = nullptr, *g_wp_p = nullptr;
    cudaGetSymbolAddress(&c_wp_p, c_wp);
    cudaGetSymbolAddress(&g_wp_p, g_wp);

    k0_pack<<<(B_ * N_ + 255) / 256, 256>>>(coords, feats, conv_w, conv_b);
    cudaMemcpyAsync(c_wp_p, g_wp_p, 64 * sizeof(float), cudaMemcpyDeviceToDevice, 0);
    k1_stats<<<(B_ * N_) / 256, 256>>>(idx);
    k3_out<<<(B_ * N_ * K_) / 256, 256>>>(idx, gamma, beta, out);
}